// round 2
// baseline (speedup 1.0000x reference)
#include <cuda_runtime.h>
#include <cstdint>

// ============================================================================
// 16-qubit statevector simulator, 64 batches, 3 layers (Rot x16 + CNOT chain).
//
// Key ideas:
//  * CNOT chain = prefix-XOR basis permutation -> folded into addressing, free.
//  * Per layer: pass A (tile = low 14 index bits) applies rotations qubits 2..15;
//    pass B (tile = bits {15,14,13} + [10:0]) applies rotations qubits 0,1 and
//    relabels for CNOT q0,q1. Last pass B measures directly (suffix-XOR parity
//    gives final-basis bits).
//  * Amplitudes live in registers (32 complex / thread, 512 threads = 2^14 tile).
//    Lane-bit gates via shfl_xor; warp-bit gates via 2 padded-smem transposes.
// ============================================================================

#define THREADS   512
#define TILE      16384
#define PAD_SLOTS (TILE + (TILE >> 5))   // 16896, pad slot = t + (t>>5)

__device__ float2 g_bufA[64 * 65536];
__device__ float2 g_bufB[64 * 65536];

struct Smem {
    float re[PAD_SLOTS];
    float im[PAD_SLOTS];
    float um[16][8];
    float feats[16];
};
#define SMEM_BYTES ((int)sizeof(Smem))

// U = Rz(tz) @ Ry(ty) @ Rx(tx), stored as {u00r,u00i,u01r,u01i,u10r,u10i,u11r,u11i}
__device__ __forceinline__ void make_u(const float* __restrict__ vp, int layer, int q,
                                       float* __restrict__ u8) {
    const float* p = vp + ((layer * 16) + q) * 6;
    float tx = p[0], ty = p[1], tz = p[2];
    float cx = cosf(0.5f * tx), sx = sinf(0.5f * tx);
    float cy = cosf(0.5f * ty), sy = sinf(0.5f * ty);
    float cz = cosf(0.5f * tz), sz = sinf(0.5f * tz);
    // M = Ry @ Rx
    float m00r =  cy * cx, m00i =  sy * sx;
    float m01r = -sy * cx, m01i = -cy * sx;
    float m10r =  sy * cx, m10i = -cy * sx;
    float m11r =  cy * cx, m11i = -sy * sx;
    // row0 *= (cz - i sz); row1 *= (cz + i sz)
    u8[0] = cz * m00r + sz * m00i;  u8[1] = cz * m00i - sz * m00r;
    u8[2] = cz * m01r + sz * m01i;  u8[3] = cz * m01i - sz * m01r;
    u8[4] = cz * m10r - sz * m10i;  u8[5] = cz * m10i + sz * m10r;
    u8[6] = cz * m11r - sz * m11i;  u8[7] = cz * m11i + sz * m11r;
}

__device__ __forceinline__ void cgate(float& ar, float& ai, float& br, float& bi,
                                      float u0, float u1, float u2, float u3,
                                      float u4, float u5, float u6, float u7) {
    float xar = ar, xai = ai, xbr = br, xbi = bi;
    ar = u0 * xar - u1 * xai + u2 * xbr - u3 * xbi;
    ai = u0 * xai + u1 * xar + u2 * xbi + u3 * xbr;
    br = u4 * xar - u5 * xai + u6 * xbr - u7 * xbi;
    bi = u4 * xai + u5 * xar + u6 * xbi + u7 * xbr;
}

// ---------------------------------------------------------------------------
// Pass A: tile = index bits [13:0] (tile id = bits [15:14]).
// Optionally applies previous layer's CNOT chain q=2..14 via load permutation
//   load_addr = i ^ ((i>>1) & 0x1FFF).
// Applies rotations on qubits 2..15 (tile bits 13..0; bit b <-> qubit 15-b).
// Mapping m1: t = (w<<10)|(r<<5)|l   (lane = low 5 bits -> coalesced)
// Mapping m2: t = (r<<9)|(l<<4)|w    (warp bits become register bits)
// ---------------------------------------------------------------------------
__global__ void __launch_bounds__(THREADS, 1)
passA(const float* __restrict__ sr, const float* __restrict__ si,
      const float2* __restrict__ src, float2* __restrict__ dst,
      const float* __restrict__ vp, int layer, int permLoad, int fromInput) {
    extern __shared__ char smraw[];
    Smem* sm = (Smem*)smraw;
    int tid = threadIdx.x;
    int w = tid >> 5, l = tid & 31;
    int batch = blockIdx.x >> 2, tile = blockIdx.x & 3;
    int base  = batch << 16;
    int tbase = tile << 14;

    if (tid < 14) make_u(vp, layer, 15 - tid, sm->um[tid]);  // um[b] : gate on bit b
    __syncthreads();

    float re[32], im[32];

    if (fromInput) {
#pragma unroll
        for (int r = 0; r < 32; r++) {
            int t = (w << 10) | (r << 5) | l;
            int i = tbase | t;
            re[r] = sr[base + i];
            im[r] = si[base + i];
        }
    } else if (permLoad) {
#pragma unroll
        for (int r = 0; r < 32; r++) {
            int t = (w << 10) | (r << 5) | l;
            int i = tbase | t;
            int a = i ^ ((i >> 1) & 0x1FFF);   // inverse of CNOT chain q=2..14
            float2 v = src[base + a];
            re[r] = v.x; im[r] = v.y;
        }
    } else {
#pragma unroll
        for (int r = 0; r < 32; r++) {
            int t = (w << 10) | (r << 5) | l;
            float2 v = src[base + (tbase | t)];
            re[r] = v.x; im[r] = v.y;
        }
    }

    // ---- gates on lane bits 0..4 (qubits 15..11) via shfl ----
#pragma unroll
    for (int b = 0; b < 5; b++) {
        float u0 = sm->um[b][0], u1 = sm->um[b][1], u2 = sm->um[b][2], u3 = sm->um[b][3];
        float u4 = sm->um[b][4], u5 = sm->um[b][5], u6 = sm->um[b][6], u7 = sm->um[b][7];
        int side = (l >> b) & 1;
        float csr = side ? u6 : u0, csi = side ? u7 : u1;
        float cpr = side ? u4 : u2, cpi = side ? u5 : u3;
#pragma unroll
        for (int r = 0; r < 32; r++) {
            float pr = __shfl_xor_sync(0xffffffffu, re[r], 1 << b);
            float pi = __shfl_xor_sync(0xffffffffu, im[r], 1 << b);
            float nr = csr * re[r] - csi * im[r] + cpr * pr - cpi * pi;
            float ni = csr * im[r] + csi * re[r] + cpr * pi + cpi * pr;
            re[r] = nr; im[r] = ni;
        }
    }

    // ---- gates on register bits 5..9 (qubits 10..6) ----
#pragma unroll
    for (int b = 5; b < 10; b++) {
        float u0 = sm->um[b][0], u1 = sm->um[b][1], u2 = sm->um[b][2], u3 = sm->um[b][3];
        float u4 = sm->um[b][4], u5 = sm->um[b][5], u6 = sm->um[b][6], u7 = sm->um[b][7];
        int s = 1 << (b - 5);
#pragma unroll
        for (int r0 = 0; r0 < 32; r0++) {
            if (r0 & s) continue;
            int r1 = r0 | s;
            cgate(re[r0], im[r0], re[r1], im[r1], u0, u1, u2, u3, u4, u5, u6, u7);
        }
    }

    // ---- transpose m1 -> m2 ----
#pragma unroll
    for (int r = 0; r < 32; r++) {
        int t = (w << 10) | (r << 5) | l;
        int slot = t + (t >> 5);
        sm->re[slot] = re[r]; sm->im[slot] = im[r];
    }
    __syncthreads();
#pragma unroll
    for (int r = 0; r < 32; r++) {
        int t = (r << 9) | (l << 4) | w;
        int slot = t + (t >> 5);
        re[r] = sm->re[slot]; im[r] = sm->im[slot];
    }

    // ---- gates on bits 10..13 (qubits 5..2): register bits 1..4 in m2 ----
#pragma unroll
    for (int b = 10; b < 14; b++) {
        float u0 = sm->um[b][0], u1 = sm->um[b][1], u2 = sm->um[b][2], u3 = sm->um[b][3];
        float u4 = sm->um[b][4], u5 = sm->um[b][5], u6 = sm->um[b][6], u7 = sm->um[b][7];
        int s = 1 << (b - 9);
#pragma unroll
        for (int r0 = 0; r0 < 32; r0++) {
            if (r0 & s) continue;
            int r1 = r0 | s;
            cgate(re[r0], im[r0], re[r1], im[r1], u0, u1, u2, u3, u4, u5, u6, u7);
        }
    }

    // ---- transpose m2 -> m1, store ----
    __syncthreads();
#pragma unroll
    for (int r = 0; r < 32; r++) {
        int t = (r << 9) | (l << 4) | w;
        int slot = t + (t >> 5);
        sm->re[slot] = re[r]; sm->im[slot] = im[r];
    }
    __syncthreads();
#pragma unroll
    for (int r = 0; r < 32; r++) {
        int t = (w << 10) | (r << 5) | l;
        int slot = t + (t >> 5);
        float2 v;
        v.x = sm->re[slot]; v.y = sm->im[slot];
        dst[base + (tbase | t)] = v;
    }
}

// ---------------------------------------------------------------------------
// Pass B: tile = global bits {15,14,13} + [10:0], tile id m = bits [12:11].
//   global g = (t[13:11] << 13) | (m << 11) | t[10:0]
// Applies rotations on qubits 0 (bit15 = t13) and 1 (bit14 = t12).
// If !measure: relabels registers for CNOT q0,q1 (i14 = j14^j15, i13 = j13^i14)
//   and stores. If measure: folds the whole CNOT chain q0..14 into the parity
//   (final bit k of index = parity(j >> k)) and accumulates Z expectations,
//   then applies the linear head via atomics.
// ---------------------------------------------------------------------------
__global__ void __launch_bounds__(THREADS, 1)
passB(const float2* __restrict__ src, float2* __restrict__ dst,
      const float* __restrict__ vp, const float* __restrict__ hw,
      float* __restrict__ out, int layer, int measure) {
    extern __shared__ char smraw[];
    Smem* sm = (Smem*)smraw;
    int tid = threadIdx.x;
    int w = tid >> 5, l = tid & 31;
    int batch = blockIdx.x >> 2, m = blockIdx.x & 3;
    int base = batch << 16;

    if (tid < 2) make_u(vp, layer, tid, sm->um[tid]);  // um[0]: qubit0, um[1]: qubit1
    if (tid < 16) sm->feats[tid] = 0.0f;
    __syncthreads();

    float re[32], im[32];
#pragma unroll
    for (int r = 0; r < 32; r++) {
        int t = (w << 10) | (r << 5) | l;
        int g = ((t >> 11) << 13) | (m << 11) | (t & 0x7FF);
        float2 v = src[base + g];
        re[r] = v.x; im[r] = v.y;
    }

    // transpose m1 -> m2 (t[13:9] become register bits)
#pragma unroll
    for (int r = 0; r < 32; r++) {
        int t = (w << 10) | (r << 5) | l;
        int slot = t + (t >> 5);
        sm->re[slot] = re[r]; sm->im[slot] = im[r];
    }
    __syncthreads();
#pragma unroll
    for (int r = 0; r < 32; r++) {
        int t = (r << 9) | (l << 4) | w;
        int slot = t + (t >> 5);
        re[r] = sm->re[slot]; im[r] = sm->im[slot];
    }

    // rotation qubit 0 (t13 = reg bit 4) and qubit 1 (t12 = reg bit 3)
#pragma unroll
    for (int gq = 0; gq < 2; gq++) {
        float u0 = sm->um[gq][0], u1 = sm->um[gq][1], u2 = sm->um[gq][2], u3 = sm->um[gq][3];
        float u4 = sm->um[gq][4], u5 = sm->um[gq][5], u6 = sm->um[gq][6], u7 = sm->um[gq][7];
        int s = gq == 0 ? 16 : 8;
#pragma unroll
        for (int r0 = 0; r0 < 32; r0++) {
            if (r0 & s) continue;
            int r1 = r0 | s;
            cgate(re[r0], im[r0], re[r1], im[r1], u0, u1, u2, u3, u4, u5, u6, u7);
        }
    }

    if (!measure) {
        // CNOT q0,q1 as register relabel: b3' = b3^b4, b2' = b2^b3'
        __syncthreads();
#pragma unroll
        for (int r = 0; r < 32; r++) {
            int b4 = (r >> 4) & 1;
            int b3 = ((r >> 3) & 1) ^ b4;
            int b2 = ((r >> 2) & 1) ^ b3;
            int rn = (r & 3) | (b2 << 2) | (b3 << 3) | (b4 << 4);
            int t = (rn << 9) | (l << 4) | w;
            int slot = t + (t >> 5);
            sm->re[slot] = re[r]; sm->im[slot] = im[r];
        }
        __syncthreads();
#pragma unroll
        for (int r = 0; r < 32; r++) {
            int t = (w << 10) | (r << 5) | l;
            int slot = t + (t >> 5);
            int g = ((t >> 11) << 13) | (m << 11) | (t & 0x7FF);
            float2 v;
            v.x = sm->re[slot]; v.y = sm->im[slot];
            dst[base + g] = v;
        }
    } else {
        float acc[16];
#pragma unroll
        for (int q = 0; q < 16; q++) acc[q] = 0.0f;
#pragma unroll
        for (int r = 0; r < 32; r++) {
            int t = (r << 9) | (l << 4) | w;
            int j = ((t >> 11) << 13) | (m << 11) | (t & 0x7FF);
            float p = re[r] * re[r] + im[r] * im[r];
            int f = j;                      // suffix-XOR: bit k of f = parity(j >> k)
            f ^= f >> 1; f ^= f >> 2; f ^= f >> 4; f ^= f >> 8;
#pragma unroll
            for (int q = 0; q < 16; q++)
                acc[q] += ((f >> (15 - q)) & 1) ? -p : p;
        }
#pragma unroll
        for (int q = 0; q < 16; q++) {
#pragma unroll
            for (int off = 16; off; off >>= 1)
                acc[q] += __shfl_xor_sync(0xffffffffu, acc[q], off);
        }
        if (l == 0) {
#pragma unroll
            for (int q = 0; q < 16; q++) atomicAdd(&sm->feats[q], acc[q]);
        }
        __syncthreads();
        if (tid == 0) {
            float v = 0.0f;
            for (int q = 0; q < 16; q++) v += sm->feats[q] * hw[q];
            atomicAdd(&out[batch], v);
        }
    }
}

__global__ void initOut(float* __restrict__ out, const float* __restrict__ hb) {
    if (threadIdx.x < 64) out[threadIdx.x] = hb[0];
}

extern "C" void kernel_launch(void* const* d_in, const int* in_sizes, int n_in,
                              void* d_out, int out_size) {
    const float* sr = (const float*)d_in[0];
    const float* si = (const float*)d_in[1];
    const float* vp = (const float*)d_in[2];
    const float* hw = (const float*)d_in[3];
    const float* hb = (const float*)d_in[4];
    float* out = (float*)d_out;

    cudaFuncSetAttribute(passA, cudaFuncAttributeMaxDynamicSharedMemorySize, SMEM_BYTES);
    cudaFuncSetAttribute(passB, cudaFuncAttributeMaxDynamicSharedMemorySize, SMEM_BYTES);

    float2 *b0, *b1;
    cudaGetSymbolAddress((void**)&b0, g_bufA);
    cudaGetSymbolAddress((void**)&b1, g_bufB);

    initOut<<<1, 64>>>(out, hb);
    // layer 0
    passA<<<256, THREADS, SMEM_BYTES>>>(sr, si, nullptr, b0, vp, 0, 0, 1);
    passB<<<256, THREADS, SMEM_BYTES>>>(b0, b1, vp, nullptr, nullptr, 0, 0);
    // layer 1 (load applies layer-0 CNOT chain q=2..14)
    passA<<<256, THREADS, SMEM_BYTES>>>(nullptr, nullptr, b1, b0, vp, 1, 1, 0);
    passB<<<256, THREADS, SMEM_BYTES>>>(b0, b1, vp, nullptr, nullptr, 1, 0);
    // layer 2
    passA<<<256, THREADS, SMEM_BYTES>>>(nullptr, nullptr, b1, b0, vp, 2, 1, 0);
    passB<<<256, THREADS, SMEM_BYTES>>>(b0, nullptr, vp, hw, out, 2, 1);
}